// round 6
// baseline (speedup 1.0000x reference)
#include <cuda_runtime.h>

// Fixed problem shape
#define NB 8      // batch
#define IC 16     // input channels
#define OC 32     // output channels
#define H  128
#define W  128
#define HP 130    // padded CS rows

typedef unsigned long long ull;

// Coefficient table: [j][i][k(padded to 4)] = (cos(theta[i*j,k]), -sin(theta[i*j,k]))
__device__ float2 g_coef[IC * OC * 4];                 // 16 KB

// Packed (cos S, sin S) for every padded row-window sum: [n*IC][HP][W], 17 MB
__device__ ull g_cs[NB * IC * HP * W];

__device__ __forceinline__ void ffma2(ull& d, ull a, ull b) {
    asm("fma.rn.f32x2 %0, %1, %2, %0;" : "+l"(d) : "l"(a), "l"(b));
}

__device__ __forceinline__ ull pack2(float lo, float hi) {
    return (ull)__float_as_uint(lo) | ((ull)__float_as_uint(hi) << 32);
}

// ---------------- Kernel 1: coef table + (cos S, sin S) tensor, fused -------
// Blocks [0,8): coefficient table (2048 entries).
// Blocks [8, 8+8320): cs tensor, one thread per (nj, hp, w).
#define CS_BLOCKS (NB * IC * HP * W / 256)   // 8320

__global__ __launch_bounds__(256)
void prep_kernel(const float* __restrict__ x, const float* __restrict__ theta) {
    if (blockIdx.x < 8) {
        int t = blockIdx.x * 256 + threadIdx.x;    // < 2048
        int j = t >> 7;
        int i = (t >> 2) & 31;
        int k = t & 3;
        float2 v = make_float2(0.f, 0.f);
        if (k < 3) {
            float th = theta[(i * j) * 3 + k];
            float s, c;
            sincosf(th, &s, &c);
            v = make_float2(c, -s);
        }
        g_coef[t] = v;
        return;
    }

    int idx = (blockIdx.x - 8) * 256 + threadIdx.x;   // total = NB*IC*HP*W
    int w    = idx & 127;
    int rowi = idx >> 7;          // nj*HP + hp
    int hp   = rowi % HP;
    int nj   = rowi / HP;
    int lane = threadIdx.x & 31;

    ull outv;
    int gr = hp - 1;
    if ((unsigned)gr < (unsigned)H) {
        const float* xr = x + ((size_t)nj * H + gr) * W;
        float v  = xr[w];
        float vm = __shfl_up_sync(0xffffffffu, v, 1);
        if (lane == 0)  vm = (w > 0)   ? xr[w - 1] : 0.f;
        float vp = __shfl_down_sync(0xffffffffu, v, 1);
        if (lane == 31) vp = (w < 127) ? xr[w + 1] : 0.f;
        float S = vm + v + vp;
        float s, c;
        __sincosf(S, &s, &c);
        outv = pack2(c, s);
    } else {
        outv = pack2(1.f, 0.f);   // S = 0 on pad rows
    }
    g_cs[idx] = outv;
}

// ---------------- Kernel 2: contraction (software-pipelined) ----------------
// grid (2, 64, 8) = (w-tile, h-tile, n). 256 threads = 8 warps.
// Warp wid owns output channels 4*wid..4*wid+3.
// Thread owns columns {w0, w0+1} (w0 = 64*wt + 2*lane), rows {h0, h0+1}.
__global__ __launch_bounds__(256, 2)
void contract_kernel(float* __restrict__ out) {
    __shared__ float2 sCoef[IC * OC * 4];   // 16 KB

    const int tid  = threadIdx.x;
    const int lane = tid & 31;
    const int wid  = tid >> 5;
    const int wt   = blockIdx.x;
    const int h0   = blockIdx.y * 2;
    const int n    = blockIdx.z;

    {
        const float4* src = reinterpret_cast<const float4*>(g_coef);
        float4* dst = reinterpret_cast<float4*>(sCoef);
        #pragma unroll
        for (int r = 0; r < 4; ++r)
            dst[tid + 256 * r] = src[tid + 256 * r];
    }
    __syncthreads();

    const int w0 = wt * 64 + 2 * lane;
    const ull* gbase = g_cs + ((size_t)n * IC * HP + h0) * W + w0;

    // acc[col][i][row], packed lo = cos-branch, hi = sin-branch
    ull acc[2][4][2];
    #pragma unroll
    for (int q = 0; q < 2; ++q)
        #pragma unroll
        for (int i = 0; i < 4; ++i) {
            acc[q][i][0] = 0ull;
            acc[q][i][1] = 0ull;
        }

    const ull* cb = reinterpret_cast<const ull*>(sCoef) + (size_t)wid * 16;

    // Prologue: load j = 0
    ulonglong2 e0, e1, e2, e3;
    {
        const ull* g = gbase;
        e0 = *reinterpret_cast<const ulonglong2*>(g + 0 * W);
        e1 = *reinterpret_cast<const ulonglong2*>(g + 1 * W);
        e2 = *reinterpret_cast<const ulonglong2*>(g + 2 * W);
        e3 = *reinterpret_cast<const ulonglong2*>(g + 3 * W);
    }

    #pragma unroll 1
    for (int j = 0; j < IC; ++j) {
        // Prefetch j+1 (guarded; predicated loads, no branch)
        ulonglong2 f0, f1, f2, f3;
        if (j < IC - 1) {
            const ull* g = gbase + (size_t)(j + 1) * HP * W;
            f0 = *reinterpret_cast<const ulonglong2*>(g + 0 * W);
            f1 = *reinterpret_cast<const ulonglong2*>(g + 1 * W);
            f2 = *reinterpret_cast<const ulonglong2*>(g + 2 * W);
            f3 = *reinterpret_cast<const ulonglong2*>(g + 3 * W);
        }

        const ull* cf = cb + (size_t)j * OC * 4;   // -> sCoef[j][4*wid][0]
        #pragma unroll
        for (int i = 0; i < 4; ++i) {
            ull c0 = cf[i * 4 + 0];
            ull c1 = cf[i * 4 + 1];
            ull c2 = cf[i * 4 + 2];
            ffma2(acc[0][i][0], e0.x, c0);
            ffma2(acc[0][i][0], e1.x, c1);
            ffma2(acc[0][i][0], e2.x, c2);
            ffma2(acc[0][i][1], e1.x, c0);
            ffma2(acc[0][i][1], e2.x, c1);
            ffma2(acc[0][i][1], e3.x, c2);
            ffma2(acc[1][i][0], e0.y, c0);
            ffma2(acc[1][i][0], e1.y, c1);
            ffma2(acc[1][i][0], e2.y, c2);
            ffma2(acc[1][i][1], e1.y, c0);
            ffma2(acc[1][i][1], e2.y, c1);
            ffma2(acc[1][i][1], e3.y, c2);
        }

        e0 = f0; e1 = f1; e2 = f2; e3 = f3;
    }

    // Epilogue: out = (lo + hi) / 3, STG.64
    #pragma unroll
    for (int i = 0; i < 4; ++i) {
        const int ig = wid * 4 + i;
        float* op = out + ((size_t)(n * OC + ig) * H + h0) * W + w0;
        #pragma unroll
        for (int r = 0; r < 2; ++r) {
            ull ax = acc[0][i][r];
            ull ay = acc[1][i][r];
            float2 o;
            o.x = (__uint_as_float((unsigned)(ax & 0xffffffffu)) +
                   __uint_as_float((unsigned)(ax >> 32))) * (1.0f / 3.0f);
            o.y = (__uint_as_float((unsigned)(ay & 0xffffffffu)) +
                   __uint_as_float((unsigned)(ay >> 32))) * (1.0f / 3.0f);
            *reinterpret_cast<float2*>(op + r * W) = o;
        }
    }
}

extern "C" void kernel_launch(void* const* d_in, const int* in_sizes, int n_in,
                              void* d_out, int out_size) {
    const float* x     = (const float*)d_in[0];   // (8,16,128,128) f32
    const float* theta = (const float*)d_in[1];   // (1536,3) f32
    float* out = (float*)d_out;                   // (8,32,128,128) f32

    prep_kernel<<<8 + CS_BLOCKS, 256>>>(x, theta);

    dim3 grid(2, H / 2, NB);                      // 1024 blocks
    contract_kernel<<<grid, 256>>>(out);
}

// round 7
// speedup vs baseline: 1.3095x; 1.3095x over previous
#include <cuda_runtime.h>

// Fixed problem shape
#define NB 8      // batch
#define IC 16     // input channels
#define OC 32     // output channels
#define H  128
#define W  128
#define HP 130    // padded CS rows
#define TH 2      // output rows per block

typedef unsigned long long ull;

// Coefficient table: [j][i][k(padded to 4)] = (cos(theta[i*j,k]), -sin(theta[i*j,k]))
__device__ float2 g_coef[IC * OC * 4];                 // 16 KB

// Packed (cos S, sin S) for every padded row-window sum: [n*IC][HP][W], 17 MB
__device__ ull g_cs[NB * IC * HP * W];

__device__ __forceinline__ void ffma2(ull& d, ull a, ull b) {
    asm("fma.rn.f32x2 %0, %1, %2, %0;" : "+l"(d) : "l"(a), "l"(b));
}

__device__ __forceinline__ ull pack2(float lo, float hi) {
    return (ull)__float_as_uint(lo) | ((ull)__float_as_uint(hi) << 32);
}

// ---------------- Kernel 1: coef table + (cos S, sin S) tensor, fused -------
#define CS_BLOCKS (NB * IC * HP * W / 256)   // 8320

__global__ __launch_bounds__(256)
void prep_kernel(const float* __restrict__ x, const float* __restrict__ theta) {
    if (blockIdx.x < 8) {
        int t = blockIdx.x * 256 + threadIdx.x;    // < 2048
        int j = t >> 7;
        int i = (t >> 2) & 31;
        int k = t & 3;
        float2 v = make_float2(0.f, 0.f);
        if (k < 3) {
            float th = theta[(i * j) * 3 + k];
            float s, c;
            sincosf(th, &s, &c);
            v = make_float2(c, -s);
        }
        g_coef[t] = v;
        return;
    }

    int idx = (blockIdx.x - 8) * 256 + threadIdx.x;   // total = NB*IC*HP*W
    int w    = idx & 127;
    int rowi = idx >> 7;          // nj*HP + hp
    int hp   = rowi % HP;
    int nj   = rowi / HP;
    int lane = threadIdx.x & 31;

    ull outv;
    int gr = hp - 1;
    if ((unsigned)gr < (unsigned)H) {
        const float* xr = x + ((size_t)nj * H + gr) * W;
        float v  = xr[w];
        float vm = __shfl_up_sync(0xffffffffu, v, 1);
        if (lane == 0)  vm = (w > 0)   ? xr[w - 1] : 0.f;
        float vp = __shfl_down_sync(0xffffffffu, v, 1);
        if (lane == 31) vp = (w < 127) ? xr[w + 1] : 0.f;
        float S = vm + v + vp;
        float s, c;
        __sincosf(S, &s, &c);
        outv = pack2(c, s);
    } else {
        outv = pack2(1.f, 0.f);   // S = 0 on pad rows
    }
    g_cs[idx] = outv;
}

// ---------------- Kernel 2: smem-fed contraction ----------------
// grid (64, 8) = (h-tile, n). 256 threads = 8 warps; warp wid owns channels
// 4*wid..4*wid+3; thread owns cols {2*lane, 2*lane+1, 64+2*lane, 64+2*lane+1}
// and rows {h0, h0+1}. Staging = pure batched LDG.128 -> STS.128 of the
// precomputed CS slab (rows hp = h0..h0+3, all 16 j). No sincos here.
__global__ __launch_bounds__(256, 2)
void contract_kernel(float* __restrict__ out) {
    __shared__ __align__(16) ull sCS[IC * 4 * W];   // 64 KB
    __shared__ float2 sCoef[IC * OC * 4];           // 16 KB

    const int tid  = threadIdx.x;
    const int lane = tid & 31;
    const int wid  = tid >> 5;
    const int h0   = blockIdx.x * TH;
    const int n    = blockIdx.y;

    // Stage coef table (1024 float4)
    {
        const float4* src = reinterpret_cast<const float4*>(g_coef);
        float4* dst = reinterpret_cast<float4*>(sCoef);
        #pragma unroll
        for (int r = 0; r < 4; ++r)
            dst[tid + 256 * r] = src[tid + 256 * r];
    }

    // Stage CS slab: 4096 ulonglong2 (16 per thread), fully independent.
    {
        const ull* gsrc = g_cs + ((size_t)n * IC * HP + h0) * W;
        #pragma unroll
        for (int it = 0; it < 16; ++it) {
            int q  = it * 256 + tid;      // 0..4095
            int w2 = q & 63;              // ulonglong2 within row
            int r  = (q >> 6) & 3;
            int j  = q >> 8;
            ulonglong2 v = *reinterpret_cast<const ulonglong2*>(
                gsrc + ((size_t)j * HP + r) * W + 2 * w2);
            *reinterpret_cast<ulonglong2*>(sCS + (j * 4 + r) * W + 2 * w2) = v;
        }
    }
    __syncthreads();   // the only barrier

    // acc[cp][col01][i][row], packed lo = cos-branch, hi = sin-branch
    ull acc[2][2][4][2];
    #pragma unroll
    for (int cp = 0; cp < 2; ++cp)
        #pragma unroll
        for (int q = 0; q < 2; ++q)
            #pragma unroll
            for (int i = 0; i < 4; ++i) {
                acc[cp][q][i][0] = 0ull;
                acc[cp][q][i][1] = 0ull;
            }

    #pragma unroll 1
    for (int j = 0; j < IC; ++j) {
        // Hoist this j's 12 coefficient pairs (warp-broadcast LDS)
        const ull* cf = reinterpret_cast<const ull*>(
            sCoef + ((size_t)j * OC + wid * 4) * 4);
        ull c0[4], c1[4], c2[4];
        #pragma unroll
        for (int i = 0; i < 4; ++i) {
            c0[i] = cf[i * 4 + 0];
            c1[i] = cf[i * 4 + 1];
            c2[i] = cf[i * 4 + 2];
        }

        const ull* base = sCS + j * 4 * W;
        #pragma unroll
        for (int cp = 0; cp < 2; ++cp) {
            const int w0 = cp * 64 + 2 * lane;
            ulonglong2 e0 = *reinterpret_cast<const ulonglong2*>(base + 0 * W + w0);
            ulonglong2 e1 = *reinterpret_cast<const ulonglong2*>(base + 1 * W + w0);
            ulonglong2 e2 = *reinterpret_cast<const ulonglong2*>(base + 2 * W + w0);
            ulonglong2 e3 = *reinterpret_cast<const ulonglong2*>(base + 3 * W + w0);
            #pragma unroll
            for (int i = 0; i < 4; ++i) {
                ffma2(acc[cp][0][i][0], e0.x, c0[i]);
                ffma2(acc[cp][0][i][0], e1.x, c1[i]);
                ffma2(acc[cp][0][i][0], e2.x, c2[i]);
                ffma2(acc[cp][0][i][1], e1.x, c0[i]);
                ffma2(acc[cp][0][i][1], e2.x, c1[i]);
                ffma2(acc[cp][0][i][1], e3.x, c2[i]);
                ffma2(acc[cp][1][i][0], e0.y, c0[i]);
                ffma2(acc[cp][1][i][0], e1.y, c1[i]);
                ffma2(acc[cp][1][i][0], e2.y, c2[i]);
                ffma2(acc[cp][1][i][1], e1.y, c0[i]);
                ffma2(acc[cp][1][i][1], e2.y, c1[i]);
                ffma2(acc[cp][1][i][1], e3.y, c2[i]);
            }
        }
    }

    // Epilogue: out = (lo + hi) / 3, STG.64
    #pragma unroll
    for (int i = 0; i < 4; ++i) {
        const int ig = wid * 4 + i;
        float* op = out + ((size_t)(n * OC + ig) * H + h0) * W;
        #pragma unroll
        for (int r = 0; r < 2; ++r)
            #pragma unroll
            for (int cp = 0; cp < 2; ++cp) {
                const int w0 = cp * 64 + 2 * lane;
                ull ax = acc[cp][0][i][r];
                ull ay = acc[cp][1][i][r];
                float2 o;
                o.x = (__uint_as_float((unsigned)(ax & 0xffffffffu)) +
                       __uint_as_float((unsigned)(ax >> 32))) * (1.0f / 3.0f);
                o.y = (__uint_as_float((unsigned)(ay & 0xffffffffu)) +
                       __uint_as_float((unsigned)(ay >> 32))) * (1.0f / 3.0f);
                *reinterpret_cast<float2*>(op + r * W + w0) = o;
            }
    }
}

extern "C" void kernel_launch(void* const* d_in, const int* in_sizes, int n_in,
                              void* d_out, int out_size) {
    const float* x     = (const float*)d_in[0];   // (8,16,128,128) f32
    const float* theta = (const float*)d_in[1];   // (1536,3) f32
    float* out = (float*)d_out;                   // (8,32,128,128) f32

    prep_kernel<<<8 + CS_BLOCKS, 256>>>(x, theta);

    dim3 grid(H / TH, NB);                        // 512 blocks
    contract_kernel<<<grid, 256>>>(out);
}